// round 3
// baseline (speedup 1.0000x reference)
#include <cuda_runtime.h>
#include <cstdint>
#include <cstddef>

#define DIN 128
#define NMAX 100000
#define EMAX 1600000
#define SCAN_B 1024

// ---------------- scratch (device globals; no allocation allowed) ----------
__device__ int   g_cnt [NMAX];
__device__ int   g_fill[NMAX];
__device__ int   g_rowptr[NMAX + 1];
__device__ int   g_bsums[128];
__device__ int   g_col[EMAX];                  // CSR column (src node)
__device__ float g_w  [EMAX];                  // CSR edge weight (norm)
__device__ float g_dinv[NMAX];
__device__ float g_T[(size_t)NMAX * 128];      // h @ W
__device__ float g_H[(size_t)NMAX * 128];      // layer activation
__device__ float g_Z[(size_t)NMAX * 64];       // final embeddings

// ---------------- CSR build --------------------------------------------------
__global__ void k_zero(int* cnt, int* fill, int n) {
    int i = blockIdx.x * blockDim.x + threadIdx.x;
    if (i < n) { cnt[i] = 0; fill[i] = 0; }
}

__global__ void k_count(const int* __restrict__ dst, int* cnt, int E) {
    int i = blockIdx.x * blockDim.x + threadIdx.x;
    if (i < E) atomicAdd(&cnt[dst[i]], 1);
}

__global__ void k_dinv(const int* __restrict__ cnt, float* __restrict__ dinv, int n) {
    int i = blockIdx.x * blockDim.x + threadIdx.x;
    if (i < n) dinv[i] = rsqrtf((float)(cnt[i] + 1));   // +1 self-loop
}

__global__ void k_scan1(const int* __restrict__ cnt, int* __restrict__ rowptr,
                        int* __restrict__ bsums, int n) {
    __shared__ int sh[SCAN_B];
    int t = threadIdx.x;
    int i = blockIdx.x * SCAN_B + t;
    int v = (i < n) ? cnt[i] : 0;
    sh[t] = v;
    __syncthreads();
    for (int o = 1; o < SCAN_B; o <<= 1) {
        int x = (t >= o) ? sh[t - o] : 0;
        __syncthreads();
        sh[t] += x;
        __syncthreads();
    }
    if (i < n) rowptr[i] = sh[t] - v;            // exclusive
    if (t == SCAN_B - 1) bsums[blockIdx.x] = sh[t];
}

__global__ void k_scan2(int* bsums, int nb, int* rowptr, int n) {
    int off = 0;
    for (int b = 0; b < nb; b++) { int s = bsums[b]; bsums[b] = off; off += s; }
    rowptr[n] = off;
}

__global__ void k_scan3(int* __restrict__ rowptr, const int* __restrict__ bsums, int n) {
    int i = blockIdx.x * blockDim.x + threadIdx.x;
    if (i < n) rowptr[i] += bsums[i >> 10];
}

__global__ void k_fill(const int* __restrict__ src, const int* __restrict__ dst,
                       const int* __restrict__ rowptr, int* __restrict__ fill,
                       const float* __restrict__ dinv,
                       int* __restrict__ col, float* __restrict__ w, int E) {
    int e = blockIdx.x * blockDim.x + threadIdx.x;
    if (e >= E) return;
    int s = src[e], d = dst[e];
    int pos = rowptr[d] + atomicAdd(&fill[d], 1);
    col[pos] = s;
    w[pos] = dinv[s] * dinv[d];
}

// ---------------- GEMM: T = X @ W  (X:[n,128] rm, W:[128,NC] rm) -----------
template <int NC>
__global__ void k_gemm(const float* __restrict__ X, const float* __restrict__ W,
                       float* __restrict__ T, int nrows) {
    constexpr int BM = 64, KC = 32, TM = 4, TN = 8;
    constexpr int BX = NC / TN;
    constexpr int NT = BX * 16;

    __shared__ float Ws[KC][NC];
    __shared__ float Xs[BM][KC + 4];

    const int tx = threadIdx.x, ty = threadIdx.y;
    const int tid = ty * BX + tx;
    const int row0 = blockIdx.x * BM;

    float acc[TM][TN] = {};

    for (int kc = 0; kc < DIN; kc += KC) {
        for (int i = tid; i < KC * NC / 4; i += NT) {
            int k = (i * 4) / NC, c = (i * 4) % NC;
            *(float4*)&Ws[k][c] = *(const float4*)(W + (size_t)(kc + k) * NC + c);
        }
        for (int i = tid; i < BM * KC / 4; i += NT) {
            int r = (i * 4) / KC, k = (i * 4) % KC;
            int rr = row0 + r; if (rr >= nrows) rr = nrows - 1;
            *(float4*)&Xs[r][k] = *(const float4*)(X + (size_t)rr * DIN + kc + k);
        }
        __syncthreads();

        #pragma unroll
        for (int k = 0; k < KC; k++) {
            float a[TM], b[TN];
            #pragma unroll
            for (int i = 0; i < TM; i++) a[i] = Xs[ty * TM + i][k];
            #pragma unroll
            for (int j = 0; j < TN; j++) b[j] = Ws[k][tx * TN + j];
            #pragma unroll
            for (int i = 0; i < TM; i++)
                #pragma unroll
                for (int j = 0; j < TN; j++)
                    acc[i][j] = fmaf(a[i], b[j], acc[i][j]);
        }
        __syncthreads();
    }

    #pragma unroll
    for (int i = 0; i < TM; i++) {
        int r = row0 + ty * TM + i;
        if (r < nrows) {
            #pragma unroll
            for (int j = 0; j < TN; j += 4)
                *(float4*)(T + (size_t)r * NC + tx * TN + j) =
                    make_float4(acc[i][j], acc[i][j+1], acc[i][j+2], acc[i][j+3]);
        }
    }
}

// ---------------- aggregate: H[i] = act( dinv[i]^2*T[i] + sum w*T[col] + b ) --
// One warp per node, NC=128: float4/lane. Atomic-free gather via CSR.
template <bool RELU>
__global__ void k_aggregate128(const float* __restrict__ T,
                               const int* __restrict__ rowptr,
                               const int* __restrict__ col,
                               const float* __restrict__ w,
                               const float* __restrict__ dinv,
                               const float* __restrict__ bias,
                               float* __restrict__ H, int n) {
    int gw = (blockIdx.x * blockDim.x + threadIdx.x) >> 5;
    int lane = threadIdx.x & 31;
    if (gw >= n) return;
    int i = gw;

    float dn = dinv[i]; dn *= dn;
    float4 t = __ldg((const float4*)(T + (size_t)i * 128) + lane);
    float4 acc = make_float4(t.x * dn, t.y * dn, t.z * dn, t.w * dn);

    int beg = rowptr[i], end = rowptr[i + 1];
    for (int j0 = beg; j0 < end; j0 += 32) {
        int idx = j0 + lane;
        int cj = 0; float wj = 0.f;
        if (idx < end) { cj = __ldg(col + idx); wj = __ldg(w + idx); }
        int m = min(32, end - j0);
        for (int t2 = 0; t2 < m; t2++) {
            int   c  = __shfl_sync(0xFFFFFFFFu, cj, t2);
            float wt = __shfl_sync(0xFFFFFFFFu, wj, t2);
            float4 v = __ldg((const float4*)(T + (size_t)c * 128) + lane);
            acc.x = fmaf(wt, v.x, acc.x);
            acc.y = fmaf(wt, v.y, acc.y);
            acc.z = fmaf(wt, v.z, acc.z);
            acc.w = fmaf(wt, v.w, acc.w);
        }
    }
    float4 b = __ldg((const float4*)bias + lane);
    acc.x += b.x; acc.y += b.y; acc.z += b.z; acc.w += b.w;
    if (RELU) {
        acc.x = fmaxf(acc.x, 0.f); acc.y = fmaxf(acc.y, 0.f);
        acc.z = fmaxf(acc.z, 0.f); acc.w = fmaxf(acc.w, 0.f);
    }
    ((float4*)(H + (size_t)i * 128))[lane] = acc;
}

// NC=64 variant: float2 per lane.
__global__ void k_aggregate64(const float* __restrict__ T,
                              const int* __restrict__ rowptr,
                              const int* __restrict__ col,
                              const float* __restrict__ w,
                              const float* __restrict__ dinv,
                              const float* __restrict__ bias,
                              float* __restrict__ Z, int n) {
    int gw = (blockIdx.x * blockDim.x + threadIdx.x) >> 5;
    int lane = threadIdx.x & 31;
    if (gw >= n) return;
    int i = gw;

    float dn = dinv[i]; dn *= dn;
    float2 t = __ldg((const float2*)(T + (size_t)i * 64) + lane);
    float2 acc = make_float2(t.x * dn, t.y * dn);

    int beg = rowptr[i], end = rowptr[i + 1];
    for (int j0 = beg; j0 < end; j0 += 32) {
        int idx = j0 + lane;
        int cj = 0; float wj = 0.f;
        if (idx < end) { cj = __ldg(col + idx); wj = __ldg(w + idx); }
        int m = min(32, end - j0);
        for (int t2 = 0; t2 < m; t2++) {
            int   c  = __shfl_sync(0xFFFFFFFFu, cj, t2);
            float wt = __shfl_sync(0xFFFFFFFFu, wj, t2);
            float2 v = __ldg((const float2*)(T + (size_t)c * 64) + lane);
            acc.x = fmaf(wt, v.x, acc.x);
            acc.y = fmaf(wt, v.y, acc.y);
        }
    }
    float2 b = __ldg((const float2*)bias + lane);
    acc.x += b.x; acc.y += b.y;
    ((float2*)(Z + (size_t)i * 64))[lane] = acc;
}

// ---------------- decode: out[p] = dot(Z[a], Z[b]) over 64 dims ------------
__global__ void k_decode(const float* __restrict__ Z, const int* __restrict__ eli,
                         float* __restrict__ out, int EL) {
    int gt = blockIdx.x * blockDim.x + threadIdx.x;
    int p = gt >> 5;
    int lane = gt & 31;
    if (p >= EL) return;
    int a = eli[p];
    int b = eli[EL + p];
    float2 za = __ldg((const float2*)(Z + (size_t)a * 64) + lane);
    float2 zb = __ldg((const float2*)(Z + (size_t)b * 64) + lane);
    float s = za.x * zb.x + za.y * zb.y;
    #pragma unroll
    for (int o = 16; o; o >>= 1) s += __shfl_xor_sync(0xFFFFFFFFu, s, o);
    if (lane == 0) out[p] = s;
}

// ---------------- launch ----------------------------------------------------
extern "C" void kernel_launch(void* const* d_in, const int* in_sizes, int n_in,
                              void* d_out, int out_size) {
    const float* x   = (const float*)d_in[0];
    const int*   ei  = (const int*)d_in[1];
    const int*   eli = (const int*)d_in[2];
    const float* W1 = (const float*)d_in[3];
    const float* b1 = (const float*)d_in[4];
    const float* W2 = (const float*)d_in[5];
    const float* b2 = (const float*)d_in[6];
    const float* W3 = (const float*)d_in[7];
    const float* b3 = (const float*)d_in[8];
    float* out = (float*)d_out;

    const int N  = in_sizes[0] / DIN;
    const int E  = in_sizes[1] / 2;
    const int EL = in_sizes[2] / 2;
    const int* src = ei;
    const int* dst = ei + E;

    int *cnt, *fill, *rowptr, *bsums, *col;
    float *w, *dinv, *T, *H, *Z;
    cudaGetSymbolAddress((void**)&cnt,    g_cnt);
    cudaGetSymbolAddress((void**)&fill,   g_fill);
    cudaGetSymbolAddress((void**)&rowptr, g_rowptr);
    cudaGetSymbolAddress((void**)&bsums,  g_bsums);
    cudaGetSymbolAddress((void**)&col,    g_col);
    cudaGetSymbolAddress((void**)&w,      g_w);
    cudaGetSymbolAddress((void**)&dinv,   g_dinv);
    cudaGetSymbolAddress((void**)&T,      g_T);
    cudaGetSymbolAddress((void**)&H,      g_H);
    cudaGetSymbolAddress((void**)&Z,      g_Z);

    const int TB = 256;
    const int nblk = (N + SCAN_B - 1) / SCAN_B;

    // ---- CSR build + norms ----
    k_zero <<<(N + TB - 1) / TB, TB>>>(cnt, fill, N);
    k_count<<<(E + TB - 1) / TB, TB>>>(dst, cnt, E);
    k_dinv <<<(N + TB - 1) / TB, TB>>>(cnt, dinv, N);
    k_scan1<<<nblk, SCAN_B>>>(cnt, rowptr, bsums, N);
    k_scan2<<<1, 1>>>(bsums, nblk, rowptr, N);
    k_scan3<<<(N + TB - 1) / TB, TB>>>(rowptr, bsums, N);
    k_fill <<<(E + TB - 1) / TB, TB>>>(src, dst, rowptr, fill, dinv, col, w, E);

    const int gblocks = (N + 63) / 64;
    const int ablocks = (int)(((size_t)N * 32 + TB - 1) / TB);

    // layer 1
    k_gemm<128><<<gblocks, dim3(16, 16)>>>(x, W1, T, N);
    k_aggregate128<true><<<ablocks, TB>>>(T, rowptr, col, w, dinv, b1, H, N);
    // layer 2
    k_gemm<128><<<gblocks, dim3(16, 16)>>>(H, W2, T, N);
    k_aggregate128<true><<<ablocks, TB>>>(T, rowptr, col, w, dinv, b2, H, N);
    // layer 3
    k_gemm<64><<<gblocks, dim3(8, 16)>>>(H, W3, T, N);
    k_aggregate64<<<ablocks, TB>>>(T, rowptr, col, w, dinv, b3, Z, N);

    // decode
    k_decode<<<(int)(((size_t)EL * 32 + TB - 1) / TB), TB>>>(Z, eli, out, EL);
}

// round 4
// speedup vs baseline: 1.6513x; 1.6513x over previous
#include <cuda_runtime.h>
#include <cstdint>
#include <cstddef>

#define DIN 128
#define NMAX 100000
#define EMAX 1600000
#define SCAN_B 1024

// ---------------- scratch (device globals; no allocation allowed) ----------
__device__ int   g_cnt [NMAX];
__device__ int   g_fill[NMAX];
__device__ int   g_rowptr[NMAX + 1];
__device__ int   g_bsums[128];
__device__ int2  g_cw[EMAX];                   // CSR packed (col, w-bits)
__device__ float g_dinv[NMAX];
__device__ float g_T[(size_t)NMAX * 128];      // h @ W
__device__ float g_H[(size_t)NMAX * 128];      // layer activation
__device__ float g_Z[(size_t)NMAX * 64];       // final embeddings

// ---------------- small PTX helpers ----------------------------------------
__device__ __forceinline__ unsigned long long ffma2(unsigned long long a,
                                                    unsigned long long b,
                                                    unsigned long long c) {
    unsigned long long d;
    asm("fma.rn.f32x2 %0, %1, %2, %3;" : "=l"(d) : "l"(a), "l"(b), "l"(c));
    return d;
}
__device__ __forceinline__ void lds_v2u64(unsigned long long& a, unsigned long long& b,
                                          unsigned addr) {
    asm volatile("ld.shared.v2.u64 {%0,%1}, [%2];" : "=l"(a), "=l"(b) : "r"(addr));
}
__device__ __forceinline__ float2 unpack2(unsigned long long v) {
    float2 f;
    asm("mov.b64 {%0,%1}, %2;" : "=f"(f.x), "=f"(f.y) : "l"(v));
    return f;
}

// ---------------- CSR build --------------------------------------------------
__global__ void k_zero(int* cnt, int* fill, int n) {
    int i = blockIdx.x * blockDim.x + threadIdx.x;
    if (i < n) { cnt[i] = 0; fill[i] = 0; }
}

__global__ void k_count(const int* __restrict__ dst, int* cnt, int E) {
    int i = blockIdx.x * blockDim.x + threadIdx.x;
    if (i < E) atomicAdd(&cnt[dst[i]], 1);
}

__global__ void k_dinv(const int* __restrict__ cnt, float* __restrict__ dinv, int n) {
    int i = blockIdx.x * blockDim.x + threadIdx.x;
    if (i < n) dinv[i] = rsqrtf((float)(cnt[i] + 1));
}

__global__ void k_scan1(const int* __restrict__ cnt, int* __restrict__ rowptr,
                        int* __restrict__ bsums, int n) {
    __shared__ int sh[SCAN_B];
    int t = threadIdx.x;
    int i = blockIdx.x * SCAN_B + t;
    int v = (i < n) ? cnt[i] : 0;
    sh[t] = v;
    __syncthreads();
    for (int o = 1; o < SCAN_B; o <<= 1) {
        int x = (t >= o) ? sh[t - o] : 0;
        __syncthreads();
        sh[t] += x;
        __syncthreads();
    }
    if (i < n) rowptr[i] = sh[t] - v;
    if (t == SCAN_B - 1) bsums[blockIdx.x] = sh[t];
}

__global__ void k_scan2(int* bsums, int nb, int* rowptr, int n) {
    int off = 0;
    for (int b = 0; b < nb; b++) { int s = bsums[b]; bsums[b] = off; off += s; }
    rowptr[n] = off;
}

__global__ void k_scan3(int* __restrict__ rowptr, const int* __restrict__ bsums, int n) {
    int i = blockIdx.x * blockDim.x + threadIdx.x;
    if (i < n) rowptr[i] += bsums[i >> 10];
}

__global__ void k_fill(const int* __restrict__ src, const int* __restrict__ dst,
                       const int* __restrict__ rowptr, int* __restrict__ fill,
                       const float* __restrict__ dinv,
                       int2* __restrict__ cw, int E) {
    int e = blockIdx.x * blockDim.x + threadIdx.x;
    if (e >= E) return;
    int s = src[e], d = dst[e];
    int pos = rowptr[d] + atomicAdd(&fill[d], 1);
    cw[pos] = make_int2(s, __float_as_int(dinv[s] * dinv[d]));
}

// ---------------- GEMM: T = X @ W via packed fma.rn.f32x2 ------------------
// BM=128 rows, BN=NC cols, KC=16. Warp tile 32x64, thread tile 8x8 (split
// fragments). X staged duplicated in shared -> a operands are natural (x,x)
// f32x2; W pairs natural from contiguous floats.
template <int NC>
__global__ void k_gemm2(const float* __restrict__ X, const float* __restrict__ W,
                        float* __restrict__ T, int nrows) {
    constexpr int BM = 128, KC = 16;
    constexpr int WCOL = NC / 64;          // 2 (NC=128) or 1 (NC=64)
    constexpr int NT = 128 * WCOL;         // 256 or 128 threads
    constexpr int XROW = 2 * BM + 4;       // 260 floats (pad 4, keeps 16B align)

    __shared__ float Xs[KC][XROW];
    __shared__ float Ws[KC][NC];

    const int tid  = threadIdx.x;
    const int warp = tid >> 5;
    const int lane = tid & 31;
    const int wr = warp & 3;               // 4 row-warps
    const int wc = warp >> 2;              // WCOL col-warps
    const int lr = lane & 3;
    const int lc = lane >> 2;
    const int row0 = blockIdx.x * BM;
    const int r0 = wr * 32 + lr * 4;       // thread's base row in block
    const int cbase = wc * 64 + lc * 4;    // thread's base col in block

    unsigned sXs = (unsigned)__cvta_generic_to_shared(&Xs[0][0]);
    unsigned sWs = (unsigned)__cvta_generic_to_shared(&Ws[0][0]);
    const unsigned aoff = sXs + (unsigned)(2 * r0) * 4u;
    const unsigned boff = sWs + (unsigned)cbase * 4u;

    unsigned long long acc2[8][4];
    #pragma unroll
    for (int i = 0; i < 8; i++)
        #pragma unroll
        for (int j = 0; j < 4; j++) acc2[i][j] = 0ull;

    for (int kc = 0; kc < DIN; kc += KC) {
        // stage W chunk [KC x NC] (vector copy)
        #pragma unroll
        for (int t = 0; t < KC * NC / 4 / NT; t++) {
            int idx = tid + t * NT;
            int k = idx / (NC / 4), c4 = idx % (NC / 4);
            *(float4*)&Ws[k][c4 * 4] = *(const float4*)(W + (size_t)(kc + k) * NC + c4 * 4);
        }
        // stage X chunk [BM x KC] transposed + duplicated
        #pragma unroll
        for (int t = 0; t < BM * KC / 4 / NT; t++) {
            int idx = tid + t * NT;
            int r = idx / (KC / 4), kq = idx % (KC / 4);
            int rr = row0 + r; if (rr >= nrows) rr = nrows - 1;
            float4 v = *(const float4*)(X + (size_t)rr * DIN + kc + kq * 4);
            *(float2*)&Xs[kq * 4 + 0][2 * r] = make_float2(v.x, v.x);
            *(float2*)&Xs[kq * 4 + 1][2 * r] = make_float2(v.y, v.y);
            *(float2*)&Xs[kq * 4 + 2][2 * r] = make_float2(v.z, v.z);
            *(float2*)&Xs[kq * 4 + 3][2 * r] = make_float2(v.w, v.w);
        }
        __syncthreads();

        #pragma unroll
        for (int k = 0; k < KC; k++) {
            unsigned long long a2[8], b2[4];
            unsigned ab = aoff + (unsigned)(k * XROW) * 4u;
            unsigned bb = boff + (unsigned)(k * NC) * 4u;
            lds_v2u64(a2[0], a2[1], ab);
            lds_v2u64(a2[2], a2[3], ab + 16u);
            lds_v2u64(a2[4], a2[5], ab + 128u);       // rows +16 (32 floats)
            lds_v2u64(a2[6], a2[7], ab + 144u);
            lds_v2u64(b2[0], b2[1], bb);
            lds_v2u64(b2[2], b2[3], bb + 128u);       // cols +32
            #pragma unroll
            for (int i = 0; i < 8; i++)
                #pragma unroll
                for (int j = 0; j < 4; j++)
                    acc2[i][j] = ffma2(a2[i], b2[j], acc2[i][j]);
        }
        __syncthreads();
    }

    // epilogue
    #pragma unroll
    for (int i = 0; i < 8; i++) {
        int r = row0 + r0 + ((i < 4) ? i : 12 + i);
        if (r < nrows) {
            float2 p0 = unpack2(acc2[i][0]), p1 = unpack2(acc2[i][1]);
            float2 p2 = unpack2(acc2[i][2]), p3 = unpack2(acc2[i][3]);
            *(float4*)(T + (size_t)r * NC + cbase)      = make_float4(p0.x, p0.y, p1.x, p1.y);
            *(float4*)(T + (size_t)r * NC + cbase + 32) = make_float4(p2.x, p2.y, p3.x, p3.y);
        }
    }
}

// ---------------- aggregate: H[i] = act( dinv^2*T[i] + sum w*T[col] + b ) --
template <bool RELU>
__global__ void k_aggregate128(const float* __restrict__ T,
                               const int* __restrict__ rowptr,
                               const int2* __restrict__ cw,
                               const float* __restrict__ dinv,
                               const float* __restrict__ bias,
                               float* __restrict__ H, int n) {
    int i = (blockIdx.x * blockDim.x + threadIdx.x) >> 5;
    int lane = threadIdx.x & 31;
    if (i >= n) return;

    float dn = dinv[i]; dn *= dn;
    float4 t = __ldg((const float4*)(T + (size_t)i * 128) + lane);
    float4 acc = make_float4(t.x * dn, t.y * dn, t.z * dn, t.w * dn);
    float4 acc1 = make_float4(0.f, 0.f, 0.f, 0.f);

    int j = rowptr[i], end = rowptr[i + 1];
    for (; j + 2 <= end; j += 2) {
        int2 e0 = __ldg(cw + j);
        int2 e1 = __ldg(cw + j + 1);
        float w0 = __int_as_float(e0.y), w1 = __int_as_float(e1.y);
        float4 v0 = __ldg((const float4*)(T + (size_t)e0.x * 128) + lane);
        float4 v1 = __ldg((const float4*)(T + (size_t)e1.x * 128) + lane);
        acc.x  = fmaf(w0, v0.x, acc.x);  acc.y  = fmaf(w0, v0.y, acc.y);
        acc.z  = fmaf(w0, v0.z, acc.z);  acc.w  = fmaf(w0, v0.w, acc.w);
        acc1.x = fmaf(w1, v1.x, acc1.x); acc1.y = fmaf(w1, v1.y, acc1.y);
        acc1.z = fmaf(w1, v1.z, acc1.z); acc1.w = fmaf(w1, v1.w, acc1.w);
    }
    if (j < end) {
        int2 e0 = __ldg(cw + j);
        float w0 = __int_as_float(e0.y);
        float4 v0 = __ldg((const float4*)(T + (size_t)e0.x * 128) + lane);
        acc.x = fmaf(w0, v0.x, acc.x); acc.y = fmaf(w0, v0.y, acc.y);
        acc.z = fmaf(w0, v0.z, acc.z); acc.w = fmaf(w0, v0.w, acc.w);
    }
    acc.x += acc1.x; acc.y += acc1.y; acc.z += acc1.z; acc.w += acc1.w;

    float4 b = __ldg((const float4*)bias + lane);
    acc.x += b.x; acc.y += b.y; acc.z += b.z; acc.w += b.w;
    if (RELU) {
        acc.x = fmaxf(acc.x, 0.f); acc.y = fmaxf(acc.y, 0.f);
        acc.z = fmaxf(acc.z, 0.f); acc.w = fmaxf(acc.w, 0.f);
    }
    ((float4*)(H + (size_t)i * 128))[lane] = acc;
}

__global__ void k_aggregate64(const float* __restrict__ T,
                              const int* __restrict__ rowptr,
                              const int2* __restrict__ cw,
                              const float* __restrict__ dinv,
                              const float* __restrict__ bias,
                              float* __restrict__ Z, int n) {
    int i = (blockIdx.x * blockDim.x + threadIdx.x) >> 5;
    int lane = threadIdx.x & 31;
    if (i >= n) return;

    float dn = dinv[i]; dn *= dn;
    float2 t = __ldg((const float2*)(T + (size_t)i * 64) + lane);
    float2 acc = make_float2(t.x * dn, t.y * dn);
    float2 acc1 = make_float2(0.f, 0.f);

    int j = rowptr[i], end = rowptr[i + 1];
    for (; j + 2 <= end; j += 2) {
        int2 e0 = __ldg(cw + j);
        int2 e1 = __ldg(cw + j + 1);
        float w0 = __int_as_float(e0.y), w1 = __int_as_float(e1.y);
        float2 v0 = __ldg((const float2*)(T + (size_t)e0.x * 64) + lane);
        float2 v1 = __ldg((const float2*)(T + (size_t)e1.x * 64) + lane);
        acc.x  = fmaf(w0, v0.x, acc.x);  acc.y  = fmaf(w0, v0.y, acc.y);
        acc1.x = fmaf(w1, v1.x, acc1.x); acc1.y = fmaf(w1, v1.y, acc1.y);
    }
    if (j < end) {
        int2 e0 = __ldg(cw + j);
        float w0 = __int_as_float(e0.y);
        float2 v0 = __ldg((const float2*)(T + (size_t)e0.x * 64) + lane);
        acc.x = fmaf(w0, v0.x, acc.x); acc.y = fmaf(w0, v0.y, acc.y);
    }
    acc.x += acc1.x; acc.y += acc1.y;

    float2 b = __ldg((const float2*)bias + lane);
    acc.x += b.x; acc.y += b.y;
    ((float2*)(Z + (size_t)i * 64))[lane] = acc;
}

// ---------------- decode -----------------------------------------------------
__global__ void k_decode(const float* __restrict__ Z, const int* __restrict__ eli,
                         float* __restrict__ out, int EL) {
    int gt = blockIdx.x * blockDim.x + threadIdx.x;
    int p = gt >> 5;
    int lane = gt & 31;
    if (p >= EL) return;
    int a = eli[p];
    int b = eli[EL + p];
    float2 za = __ldg((const float2*)(Z + (size_t)a * 64) + lane);
    float2 zb = __ldg((const float2*)(Z + (size_t)b * 64) + lane);
    float s = za.x * zb.x + za.y * zb.y;
    #pragma unroll
    for (int o = 16; o; o >>= 1) s += __shfl_xor_sync(0xFFFFFFFFu, s, o);
    if (lane == 0) out[p] = s;
}

// ---------------- launch ----------------------------------------------------
extern "C" void kernel_launch(void* const* d_in, const int* in_sizes, int n_in,
                              void* d_out, int out_size) {
    const float* x   = (const float*)d_in[0];
    const int*   ei  = (const int*)d_in[1];
    const int*   eli = (const int*)d_in[2];
    const float* W1 = (const float*)d_in[3];
    const float* b1 = (const float*)d_in[4];
    const float* W2 = (const float*)d_in[5];
    const float* b2 = (const float*)d_in[6];
    const float* W3 = (const float*)d_in[7];
    const float* b3 = (const float*)d_in[8];
    float* out = (float*)d_out;

    const int N  = in_sizes[0] / DIN;
    const int E  = in_sizes[1] / 2;
    const int EL = in_sizes[2] / 2;
    const int* src = ei;
    const int* dst = ei + E;

    int *cnt, *fill, *rowptr, *bsums;
    int2* cw;
    float *dinv, *T, *H, *Z;
    cudaGetSymbolAddress((void**)&cnt,    g_cnt);
    cudaGetSymbolAddress((void**)&fill,   g_fill);
    cudaGetSymbolAddress((void**)&rowptr, g_rowptr);
    cudaGetSymbolAddress((void**)&bsums,  g_bsums);
    cudaGetSymbolAddress((void**)&cw,     g_cw);
    cudaGetSymbolAddress((void**)&dinv,   g_dinv);
    cudaGetSymbolAddress((void**)&T,      g_T);
    cudaGetSymbolAddress((void**)&H,      g_H);
    cudaGetSymbolAddress((void**)&Z,      g_Z);

    const int TB = 256;
    const int nblk = (N + SCAN_B - 1) / SCAN_B;

    k_zero <<<(N + TB - 1) / TB, TB>>>(cnt, fill, N);
    k_count<<<(E + TB - 1) / TB, TB>>>(dst, cnt, E);
    k_dinv <<<(N + TB - 1) / TB, TB>>>(cnt, dinv, N);
    k_scan1<<<nblk, SCAN_B>>>(cnt, rowptr, bsums, N);
    k_scan2<<<1, 1>>>(bsums, nblk, rowptr, N);
    k_scan3<<<(N + TB - 1) / TB, TB>>>(rowptr, bsums, N);
    k_fill <<<(E + TB - 1) / TB, TB>>>(src, dst, rowptr, fill, dinv, cw, E);

    const int gblocks = (N + 127) / 128;
    const int ablocks = (int)(((size_t)N * 32 + TB - 1) / TB);

    // layer 1
    k_gemm2<128><<<gblocks, 256>>>(x, W1, T, N);
    k_aggregate128<true><<<ablocks, TB>>>(T, rowptr, cw, dinv, b1, H, N);
    // layer 2
    k_gemm2<128><<<gblocks, 256>>>(H, W2, T, N);
    k_aggregate128<true><<<ablocks, TB>>>(T, rowptr, cw, dinv, b2, H, N);
    // layer 3
    k_gemm2<64><<<gblocks, 128>>>(H, W3, T, N);
    k_aggregate64<<<ablocks, TB>>>(T, rowptr, cw, dinv, b3, Z, N);

    // decode
    k_decode<<<(int)(((size_t)EL * 32 + TB - 1) / TB), TB>>>(Z, eli, out, EL);
}